// round 12
// baseline (speedup 1.0000x reference)
#include <cuda_runtime.h>
#include <cstdint>
#include <cstddef>

// SNN Leaky scan. reset_t = H(mem_{t-1}-1); mem_t = beta*mem_{t-1}+x_t-reset_t; spk_t = H(mem_t-1)
//
// Recurrence (bit-identical to reference; rel_err 0 verified in R11):
//   a_t   = __fmaf_rn(beta, mem_{t-1}, x_t);   mem_t = a_t - rf_{t-1}   (exact, Sterbenz)
//   m1 = sgn(1 - a_t), m2 = sgn(2 - a_t)       (FADD+SHR, off the carried cycle)
//   mask_t = m2&mask_{t-1} | m1&~mask_{t-1}    (single LOP3 carried dep)
//   rf_t   = float_bits(mask_t & 0x3F800000)   ({0.0f,1.0f}; no I2F, no predicates)
//
// KEY CHANGE vs R11 (best, 72.2us): TCHUNK 128 -> 160. 4000 = 25*160 exactly:
// 22% fewer chunks => 22% fewer barrier rounds / group commits / pipeline refills,
// and the tail path disappears. Everything else frozen (256 CTAs x 32 rows,
// 1 compute + 1 io warp, 3-in/2-out ring, odd stride -> conflict-free LDS/STS.128).

namespace {
constexpr int N_TOTAL  = 8192;
constexpr int T_STEPS  = 4000;
constexpr float BETA   = 0.95f;

constexpr int ROWS     = 32;     // rows per CTA (1 per compute lane)
constexpr int CTHREADS = 32;     // compute warp
constexpr int THREADS  = 64;     // + 1 io warp
constexpr int TCHUNK   = 160;    // 25 * 160 = 4000 exactly (no tail)
constexpr int TC4      = TCHUNK / 4;          // 40 float4 per row-chunk
constexpr int NCHUNK   = T_STEPS / TCHUNK;    // 25
constexpr int RSTRIDE  = TC4 + 1;             // 41: odd stride, conflict-free LDS/STS
constexpr int BUFELEM  = ROWS * RSTRIDE;      // 1312 float4 per buffer
constexpr size_t SMEM_BYTES = (size_t)(3 + 2) * BUFELEM * sizeof(float4);  // 105 KB
}

__device__ __forceinline__ void cp_async16(void* sdst, const void* gsrc) {
    uint32_t s = (uint32_t)__cvta_generic_to_shared(sdst);
    asm volatile("cp.async.cg.shared.global [%0], [%1], 16;" :: "r"(s), "l"(gsrc));
}
__device__ __forceinline__ void cp_commit() {
    asm volatile("cp.async.commit_group;" ::: "memory");
}
template <int NN>
__device__ __forceinline__ void cp_wait() {
    asm volatile("cp.async.wait_group %0;" :: "n"(NN) : "memory");
}

// all-ones iff v < 0 (sign splat): arithmetic shift, lat 4
__device__ __forceinline__ uint32_t sgnmask(float v) {
    return (uint32_t)(__float_as_int(v) >> 31);
}
// (b & c) | (a & ~c) as a single LOP3, lat 4
__device__ __forceinline__ uint32_t lop3_sel(uint32_t a, uint32_t b, uint32_t c) {
    uint32_t r;
    asm("lop3.b32 %0, %1, %2, %3, 0xD8;" : "=r"(r) : "r"(a), "r"(b), "r"(c));
    return r;
}

struct SnnState {
    float mem;      // mem_{t-1}  (bit-identical to reference recurrence)
    float rf;       // r_{t-1} as float in {0.0f, 1.0f}
    uint32_t mask;  // splat of spk_{t-1}
};

__device__ __forceinline__ float snn_step(SnnState& s, float x) {
    float a = __fmaf_rn(BETA, s.mem, x);
    s.mem = a - s.rf;                      // exact (Sterbenz)
    uint32_t m1 = sgnmask(1.0f - a);       // [a > 1]
    uint32_t m2 = sgnmask(2.0f - a);       // [a > 2]
    s.mask = lop3_sel(m1, m2, s.mask);     // spk_t splat
    s.rf = __uint_as_float(s.mask & 0x3F800000u);
    return s.rf;
}

__device__ __forceinline__ float4 snn_step4(SnnState& s, float4 x) {
    float4 o;
    o.x = snn_step(s, x.x);
    o.y = snn_step(s, x.y);
    o.z = snn_step(s, x.z);
    o.w = snn_step(s, x.w);
    return o;
}

__global__ void __launch_bounds__(THREADS, 2)
snn_leaky_ws_kernel(const float* __restrict__ inp, float* __restrict__ out) {
    extern __shared__ float4 smem[];
    const int tid  = threadIdx.x;
    const int lane = tid & 31;
    const int rowBase = blockIdx.x * ROWS;
    const bool is_io = (tid >= CTHREADS);

    float4* inbuf[3]  = { smem, smem + BUFELEM, smem + 2 * BUFELEM };
    float4* outbuf[2] = { smem + 3 * BUFELEM, smem + 4 * BUFELEM };

    // ---- prologue: io warp preloads chunks 0 and 1 (one commit group each) ----
    if (is_io) {
        #pragma unroll
        for (int c0 = 0; c0 < 2; ++c0) {
            #pragma unroll
            for (int r = 0; r < ROWS; ++r) {
                const float4* g = reinterpret_cast<const float4*>(
                    inp + (size_t)(rowBase + r) * T_STEPS + c0 * TCHUNK);
                float4* d = &inbuf[c0][r * RSTRIDE];
                #pragma unroll
                for (int i = lane; i < TC4; i += 32) cp_async16(d + i, g + i);
            }
            cp_commit();
        }
    }

    SnnState st;
    st.mem = 0.0f; st.rf = 0.0f; st.mask = 0u;

    for (int c = 0; c <= NCHUNK; ++c) {
        if (is_io) cp_wait<1>();   // input chunk c landed (<=1 group outstanding)
        __syncthreads();

        if (!is_io) {
            if (c < NCHUNK) {
                const float4* __restrict__ rin  = inbuf[c % 3] + lane * RSTRIDE;
                float4* __restrict__       rout = outbuf[c & 1] + lane * RSTRIDE;
                float4 xa = rin[0];            // LDS pipelined 2 iters ahead
                float4 xb = rin[1];
                #pragma unroll
                for (int t4 = 0; t4 < TC4; ++t4) {
                    float4 xc;
                    if (t4 + 2 < TC4) xc = rin[t4 + 2];
                    rout[t4] = snn_step4(st, xa);
                    xa = xb; xb = xc;
                }
            }
        } else {
            // ---- store spikes of chunk c-1 (coalesced float4 STG) ----
            if (c >= 1) {
                const int cp = c - 1;
                const float4* b = outbuf[cp & 1];
                #pragma unroll 2
                for (int r = 0; r < ROWS; ++r) {
                    float4* g = reinterpret_cast<float4*>(
                        out + (size_t)(rowBase + r) * T_STEPS + cp * TCHUNK);
                    const float4* s = &b[r * RSTRIDE];
                    #pragma unroll
                    for (int i = lane; i < TC4; i += 32) g[i] = s[i];
                }
            }
            // ---- prefetch input chunk c+2 ----
            if (c + 2 < NCHUNK) {
                const int cn = c + 2;
                float4* b = inbuf[cn % 3];
                #pragma unroll 2
                for (int r = 0; r < ROWS; ++r) {
                    const float4* g = reinterpret_cast<const float4*>(
                        inp + (size_t)(rowBase + r) * T_STEPS + cn * TCHUNK);
                    float4* d = &b[r * RSTRIDE];
                    #pragma unroll
                    for (int i = lane; i < TC4; i += 32) cp_async16(d + i, g + i);
                }
            }
            cp_commit();   // unconditional: uniform group counting
        }
    }
}

extern "C" void kernel_launch(void* const* d_in, const int* in_sizes, int n_in,
                              void* d_out, int out_size) {
    (void)in_sizes; (void)n_in; (void)out_size;
    const float* inp = (const float*)d_in[0];
    float* out = (float*)d_out;

    cudaFuncSetAttribute(snn_leaky_ws_kernel,
                         cudaFuncAttributeMaxDynamicSharedMemorySize,
                         (int)SMEM_BYTES);
    snn_leaky_ws_kernel<<<N_TOTAL / ROWS, THREADS, SMEM_BYTES>>>(inp, out);
}

// round 13
// speedup vs baseline: 1.4514x; 1.4514x over previous
#include <cuda_runtime.h>
#include <cstdint>
#include <cstddef>

// SNN Leaky scan. reset_t = H(mem_{t-1}-1); mem_t = beta*mem_{t-1}+x_t-reset_t; spk_t = H(mem_t-1)
//
// Recurrence (bit-identical to reference; rel_err 0 verified in R11):
//   a_t   = __fmaf_rn(beta, mem_{t-1}, x_t);   mem_t = a_t - rf_{t-1}   (exact, Sterbenz)
//   m1 = sgn(1 - a_t), m2 = sgn(2 - a_t)       (FADD+SHR, off the carried cycle)
//   mask_t = m2&mask_{t-1} | m1&~mask_{t-1}    (single LOP3 carried dep)
//   rf_t   = float_bits(mask_t & 0x3F800000)   ({0.0f,1.0f}; no I2F, no predicates)
//
// Config = R11 (best 72.2us) with ONE change: io split into two warps.
//   warp 0: compute (1 row/lane)
//   warp 1: loader  (cp.async prefetch 2 chunks ahead + cp_wait)
//   warp 2: storer  (coalesced float4 STG of previous chunk's spikes)
// Halves the io critical path per chunk and decouples cp_wait from the stores.
// 256 CTAs x 32 rows, TCHUNK=128 (TC4=32: one f4 per lane per row, zero divergence),
// 3-in/2-out SMEM ring, odd row stride (33 f4) -> conflict-free LDS/STS.128.

namespace {
constexpr int N_TOTAL  = 8192;
constexpr int T_STEPS  = 4000;
constexpr float BETA   = 0.95f;

constexpr int ROWS     = 32;     // rows per CTA (1 per compute lane)
constexpr int THREADS  = 96;     // warp0 compute, warp1 loader, warp2 storer
constexpr int TCHUNK   = 128;    // time steps per chunk
constexpr int TC4      = TCHUNK / 4;                          // 32 float4 per row-chunk
constexpr int NCHUNK   = (T_STEPS + TCHUNK - 1) / TCHUNK;     // 32 (31 full + 32-step tail)
constexpr int TAIL4    = (T_STEPS - (NCHUNK - 1) * TCHUNK) / 4;  // 8
constexpr int RSTRIDE  = TC4 + 1;                             // 33: odd stride, conflict-free
constexpr int BUFELEM  = ROWS * RSTRIDE;                      // float4 per buffer
constexpr size_t SMEM_BYTES = (size_t)(3 + 2) * BUFELEM * sizeof(float4);  // 84.5 KB
}

__device__ __forceinline__ void cp_async16(void* sdst, const void* gsrc) {
    uint32_t s = (uint32_t)__cvta_generic_to_shared(sdst);
    asm volatile("cp.async.cg.shared.global [%0], [%1], 16;" :: "r"(s), "l"(gsrc));
}
__device__ __forceinline__ void cp_commit() {
    asm volatile("cp.async.commit_group;" ::: "memory");
}
template <int NN>
__device__ __forceinline__ void cp_wait() {
    asm volatile("cp.async.wait_group %0;" :: "n"(NN) : "memory");
}

// all-ones iff v < 0 (sign splat): arithmetic shift, lat 4
__device__ __forceinline__ uint32_t sgnmask(float v) {
    return (uint32_t)(__float_as_int(v) >> 31);
}
// (b & c) | (a & ~c) as a single LOP3, lat 4
__device__ __forceinline__ uint32_t lop3_sel(uint32_t a, uint32_t b, uint32_t c) {
    uint32_t r;
    asm("lop3.b32 %0, %1, %2, %3, 0xD8;" : "=r"(r) : "r"(a), "r"(b), "r"(c));
    return r;
}

struct SnnState {
    float mem;      // mem_{t-1}  (bit-identical to reference recurrence)
    float rf;       // r_{t-1} as float in {0.0f, 1.0f}
    uint32_t mask;  // splat of spk_{t-1}
};

__device__ __forceinline__ float snn_step(SnnState& s, float x) {
    float a = __fmaf_rn(BETA, s.mem, x);
    s.mem = a - s.rf;                      // exact (Sterbenz)
    uint32_t m1 = sgnmask(1.0f - a);       // [a > 1]
    uint32_t m2 = sgnmask(2.0f - a);       // [a > 2]
    s.mask = lop3_sel(m1, m2, s.mask);     // spk_t splat
    s.rf = __uint_as_float(s.mask & 0x3F800000u);
    return s.rf;
}

__device__ __forceinline__ float4 snn_step4(SnnState& s, float4 x) {
    float4 o;
    o.x = snn_step(s, x.x);
    o.y = snn_step(s, x.y);
    o.z = snn_step(s, x.z);
    o.w = snn_step(s, x.w);
    return o;
}

__global__ void __launch_bounds__(THREADS, 2)
snn_leaky_ws_kernel(const float* __restrict__ inp, float* __restrict__ out) {
    extern __shared__ float4 smem[];
    const int tid  = threadIdx.x;
    const int lane = tid & 31;
    const int wid  = tid >> 5;            // 0 compute, 1 loader, 2 storer
    const int rowBase = blockIdx.x * ROWS;

    float4* inbuf[3]  = { smem, smem + BUFELEM, smem + 2 * BUFELEM };
    float4* outbuf[2] = { smem + 3 * BUFELEM, smem + 4 * BUFELEM };

    // ---- prologue: loader warp preloads chunks 0 and 1 (one commit group each) ----
    if (wid == 1) {
        #pragma unroll
        for (int c0 = 0; c0 < 2; ++c0) {
            #pragma unroll
            for (int r = 0; r < ROWS; ++r) {
                const float4* g = reinterpret_cast<const float4*>(
                    inp + (size_t)(rowBase + r) * T_STEPS + c0 * TCHUNK);
                cp_async16(&inbuf[c0][r * RSTRIDE + lane], g + lane);
            }
            cp_commit();
        }
    }

    SnnState st;
    st.mem = 0.0f; st.rf = 0.0f; st.mask = 0u;

    for (int c = 0; c <= NCHUNK; ++c) {
        if (wid == 1) cp_wait<1>();   // input chunk c landed (<=1 group outstanding)
        __syncthreads();

        if (wid == 0) {
            // ---- compute chunk c: 1 row per lane, spikes -> outbuf ----
            if (c < NCHUNK) {
                const float4* __restrict__ rin  = inbuf[c % 3] + lane * RSTRIDE;
                float4* __restrict__       rout = outbuf[c & 1] + lane * RSTRIDE;
                if (c != NCHUNK - 1) {
                    float4 xa = rin[0];            // LDS pipelined 2 iters ahead
                    float4 xb = rin[1];
                    #pragma unroll
                    for (int t4 = 0; t4 < TC4; ++t4) {
                        float4 xc;
                        if (t4 + 2 < TC4) xc = rin[t4 + 2];
                        rout[t4] = snn_step4(st, xa);
                        xa = xb; xb = xc;
                    }
                } else {
                    float4 xa = rin[0];
                    float4 xb = rin[1];
                    #pragma unroll
                    for (int t4 = 0; t4 < TAIL4; ++t4) {
                        float4 xc;
                        if (t4 + 2 < TAIL4) xc = rin[t4 + 2];
                        rout[t4] = snn_step4(st, xa);
                        xa = xb; xb = xc;
                    }
                }
            }
        } else if (wid == 2) {
            // ---- storer: spikes of chunk c-1 (coalesced float4 STG) ----
            if (c >= 1) {
                const int cp = c - 1;
                const int nv4 = (cp == NCHUNK - 1) ? TAIL4 : TC4;
                const float4* b = outbuf[cp & 1];
                if (lane < nv4) {
                    #pragma unroll 4
                    for (int r = 0; r < ROWS; ++r) {
                        float4 v = b[r * RSTRIDE + lane];
                        reinterpret_cast<float4*>(
                            out + (size_t)(rowBase + r) * T_STEPS + cp * TCHUNK)[lane] = v;
                    }
                }
            }
        } else {
            // ---- loader: prefetch input chunk c+2 ----
            if (c + 2 < NCHUNK) {
                const int cn = c + 2;
                const int nvn = (cn == NCHUNK - 1) ? TAIL4 : TC4;
                float4* b = inbuf[cn % 3];
                if (lane < nvn) {
                    #pragma unroll 4
                    for (int r = 0; r < ROWS; ++r) {
                        const float4* g = reinterpret_cast<const float4*>(
                            inp + (size_t)(rowBase + r) * T_STEPS + cn * TCHUNK);
                        cp_async16(&b[r * RSTRIDE + lane], g + lane);
                    }
                }
            }
            cp_commit();   // loader only: uniform group counting per loader thread
        }
    }
}

extern "C" void kernel_launch(void* const* d_in, const int* in_sizes, int n_in,
                              void* d_out, int out_size) {
    (void)in_sizes; (void)n_in; (void)out_size;
    const float* inp = (const float*)d_in[0];
    float* out = (float*)d_out;

    cudaFuncSetAttribute(snn_leaky_ws_kernel,
                         cudaFuncAttributeMaxDynamicSharedMemorySize,
                         (int)SMEM_BYTES);
    snn_leaky_ws_kernel<<<N_TOTAL / ROWS, THREADS, SMEM_BYTES>>>(inp, out);
}